// round 1
// baseline (speedup 1.0000x reference)
#include <cuda_runtime.h>
#include <cuda_fp16.h>
#include <cstdint>

#define B_ 64
#define F_ 4
#define M_ 4096
#define D_ 1024
#define ITERS_ 15

// ---------------- device scratch (no allocations allowed) ----------------
__device__ __half g_Ch[F_ * M_ * D_];      // codebooks as fp16 +-1, [f][m][d]   (32 MB)
__device__ __half g_G[F_ * D_ * D_];       // (C^T C)/2 as fp16, [f][d1][d2]     (8 MB, symmetric)
__device__ __half g_est[2][F_ * B_ * D_];  // ping-pong estimates +-1, [f][b][d]
__device__ __half g_ne[F_ * B_ * D_];      // new_est (unbound) +-1, [f][b][d]
__device__ __half g_inp[B_ * D_];          // input +-1, [b][d]
__device__ int    g_diff[ITERS_];          // 1 if estimates changed at iter i
__device__ int    g_amax[B_ * F_];         // packed argmax keys

__device__ __forceinline__ __half sgnh(float x) {
    return __float2half(x >= 0.f ? 1.f : -1.f);
}

__device__ __forceinline__ void mma16816(float* c, const unsigned* a, unsigned b0, unsigned b1) {
    asm volatile(
        "mma.sync.aligned.m16n8k16.row.col.f32.f16.f16.f32 "
        "{%0,%1,%2,%3}, {%4,%5,%6,%7}, {%8,%9}, {%0,%1,%2,%3};\n"
        : "+f"(c[0]), "+f"(c[1]), "+f"(c[2]), "+f"(c[3])
        : "r"(a[0]), "r"(a[1]), "r"(a[2]), "r"(a[3]), "r"(b0), "r"(b1));
}

// ---------------- conversion / init ----------------
__global__ __launch_bounds__(256) void k_convert_cb(const float4* cb) {
    const int n = F_ * M_ * D_ / 4;
    __half2* out = reinterpret_cast<__half2*>(g_Ch);
    for (int i = blockIdx.x * blockDim.x + threadIdx.x; i < n; i += gridDim.x * blockDim.x) {
        float4 v = cb[i];
        out[2 * i]     = __halves2half2(sgnh(v.x), sgnh(v.y));
        out[2 * i + 1] = __halves2half2(sgnh(v.z), sgnh(v.w));
    }
}

__global__ __launch_bounds__(256) void k_init(const float* inp, const float* ie) {
    int tid = blockIdx.x * blockDim.x + threadIdx.x;
    int stride = gridDim.x * blockDim.x;
    for (int i = tid; i < B_ * D_; i += stride) g_inp[i] = sgnh(inp[i]);
    for (int i = tid; i < B_ * F_ * D_; i += stride) {
        int b = i / (F_ * D_);
        int f = (i / D_) % F_;
        int d = i % D_;
        g_est[0][(f * B_ + b) * D_ + d] = sgnh(ie[i]);
    }
    if (tid < ITERS_) g_diff[tid] = 0;
    for (int i = tid; i < B_ * F_; i += stride) g_amax[i] = -1;
}

// ---------------- Gram matrix: G = (C^T C)/2, fp16 ----------------
// grid (8, 8, 4) = (d1 tile, d2 tile, f); CTA tile 128x128, K chunk 16, 8 warps (2x4).
__global__ __launch_bounds__(256) void k_gram() {
    __shared__ __half As[128][18];  // [d1][k]
    __shared__ __half Bs[128][18];  // [d2][k]
    const int f = blockIdx.z;
    const int d1b = blockIdx.x * 128, d2b = blockIdx.y * 128;
    const int tid = threadIdx.x, lane = tid & 31, w = tid >> 5;
    const int wm = w >> 2, wn = w & 3;   // 2 x 4 warp grid
    const int mr = wm * 64, nc = wn * 32;

    float acc[4][4][4];
#pragma unroll
    for (int i = 0; i < 4; i++)
#pragma unroll
        for (int j = 0; j < 4; j++)
#pragma unroll
            for (int q = 0; q < 4; q++) acc[i][j][q] = 0.f;

    const __half* C = g_Ch + (size_t)f * M_ * D_;
    const int kr = tid >> 4;        // 0..15
    const int cg = (tid & 15) * 8;  // 0..120

    for (int k0 = 0; k0 < M_; k0 += 16) {
        uint4 va = *(const uint4*)(C + (size_t)(k0 + kr) * D_ + d1b + cg);
        uint4 vb = *(const uint4*)(C + (size_t)(k0 + kr) * D_ + d2b + cg);
        const __half* pa = (const __half*)&va;
        const __half* pb = (const __half*)&vb;
#pragma unroll
        for (int j = 0; j < 8; j++) { As[cg + j][kr] = pa[j]; Bs[cg + j][kr] = pb[j]; }
        __syncthreads();

        unsigned a[4][4], bb[4][2];
        const int c = (lane & 3) * 2;
#pragma unroll
        for (int i = 0; i < 4; i++) {
            int r = mr + i * 16 + (lane >> 2);
            a[i][0] = *(const unsigned*)&As[r][c];
            a[i][1] = *(const unsigned*)&As[r + 8][c];
            a[i][2] = *(const unsigned*)&As[r][c + 8];
            a[i][3] = *(const unsigned*)&As[r + 8][c + 8];
        }
#pragma unroll
        for (int j = 0; j < 4; j++) {
            int n = nc + j * 8 + (lane >> 2);
            bb[j][0] = *(const unsigned*)&Bs[n][c];
            bb[j][1] = *(const unsigned*)&Bs[n][c + 8];
        }
#pragma unroll
        for (int i = 0; i < 4; i++)
#pragma unroll
            for (int j = 0; j < 4; j++) mma16816(acc[i][j], a[i], bb[j][0], bb[j][1]);
        __syncthreads();
    }

#pragma unroll
    for (int i = 0; i < 4; i++) {
        int r0 = d1b + mr + i * 16 + (lane >> 2);
#pragma unroll
        for (int j = 0; j < 4; j++) {
            int c0 = d2b + nc + j * 8 + (lane & 3) * 2;
            *(__half2*)(g_G + (size_t)(f * D_ + r0) * D_ + c0) =
                __floats2half2_rn(acc[i][j][0] * 0.5f, acc[i][j][1] * 0.5f);
            *(__half2*)(g_G + (size_t)(f * D_ + r0 + 8) * D_ + c0) =
                __floats2half2_rn(acc[i][j][2] * 0.5f, acc[i][j][3] * 0.5f);
        }
    }
}

// ---------------- per-iteration: new_est (unbind) ----------------
__global__ __launch_bounds__(256) void k_newest(int cur) {
    const int n = B_ * D_ / 2;
    const __half2* inp2 = (const __half2*)g_inp;
    const __half2* e = (const __half2*)g_est[cur];
    __half2* ne = (__half2*)g_ne;
    for (int i = blockIdx.x * blockDim.x + threadIdx.x; i < n; i += gridDim.x * blockDim.x) {
        __half2 e0 = e[i], e1 = e[n + i], e2 = e[2 * n + i], e3 = e[3 * n + i];
        __half2 t = __hmul2(__hmul2(__hmul2(__hmul2(inp2[i], e0), e1), e2), e3);
        ne[i]         = __hmul2(t, e0);
        ne[n + i]     = __hmul2(t, e1);
        ne[2 * n + i] = __hmul2(t, e2);
        ne[3 * n + i] = __hmul2(t, e3);
    }
}

// ---------------- per-iteration: upd = sign(G @ ne) ----------------
// grid (16, 4) = (d1 tile, f); CTA tile 64(b) x 64(d1), K chunk 32, 8 warps (4x2).
__global__ __launch_bounds__(256) void k_iter(int cur, int it) {
    __shared__ __half As[64][40];   // [b][k]
    __shared__ __half Bs[64][40];   // [d1][k]  (G row-major works: G symmetric)
    const int f = blockIdx.y;
    const int d1b = blockIdx.x * 64;
    const int tid = threadIdx.x, lane = tid & 31, w = tid >> 5;
    const int wm = w >> 1, wn = w & 1;
    const int mr = wm * 16, nc = wn * 32;

    float acc[4][4];
#pragma unroll
    for (int j = 0; j < 4; j++)
#pragma unroll
        for (int q = 0; q < 4; q++) acc[j][q] = 0.f;

    const __half* A = g_ne + (size_t)f * B_ * D_;
    const __half* Bm = g_G + (size_t)f * D_ * D_;
    const int rb = tid >> 2;            // 0..63
    const int kg = (tid & 3) * 8;       // 0..24

    for (int k0 = 0; k0 < D_; k0 += 32) {
        *(uint4*)&As[rb][kg] = *(const uint4*)(A + (size_t)rb * D_ + k0 + kg);
        *(uint4*)&Bs[rb][kg] = *(const uint4*)(Bm + (size_t)(d1b + rb) * D_ + k0 + kg);
        __syncthreads();
#pragma unroll
        for (int kk = 0; kk < 2; kk++) {
            const int c = kk * 16 + (lane & 3) * 2;
            unsigned a[4];
            int r = mr + (lane >> 2);
            a[0] = *(const unsigned*)&As[r][c];
            a[1] = *(const unsigned*)&As[r + 8][c];
            a[2] = *(const unsigned*)&As[r][c + 8];
            a[3] = *(const unsigned*)&As[r + 8][c + 8];
#pragma unroll
            for (int j = 0; j < 4; j++) {
                int n = nc + j * 8 + (lane >> 2);
                unsigned b0 = *(const unsigned*)&Bs[n][c];
                unsigned b1 = *(const unsigned*)&Bs[n][c + 8];
                mma16816(acc[j], a, b0, b1);
            }
        }
        __syncthreads();
    }

    __half* enew = g_est[cur ^ 1] + (size_t)f * B_ * D_;
    const __half* eold = g_est[cur] + (size_t)f * B_ * D_;
    bool changed = false;
#pragma unroll
    for (int j = 0; j < 4; j++) {
        int col = d1b + nc + j * 8 + (lane & 3) * 2;
        int r0 = mr + (lane >> 2);
#pragma unroll
        for (int half_ = 0; half_ < 2; half_++) {
            int r = r0 + half_ * 8;
            __half s0 = acc[j][half_ * 2] >= 0.f ? __float2half(1.f) : __float2half(-1.f);
            __half s1 = acc[j][half_ * 2 + 1] >= 0.f ? __float2half(1.f) : __float2half(-1.f);
            __half2 old = *(const __half2*)(eold + (size_t)r * D_ + col);
            *(__half2*)(enew + (size_t)r * D_ + col) = __halves2half2(s0, s1);
            changed |= (__half_as_ushort(s0) != __half_as_ushort(__low2half(old)));
            changed |= (__half_as_ushort(s1) != __half_as_ushort(__high2half(old)));
        }
    }
    unsigned mask = __ballot_sync(0xffffffffu, changed);
    if (lane == 0 && mask) atomicOr(&g_diff[it], 1);
}

// ---------------- cleanup: sim = est @ C^T, fused |.| argmax ----------------
// grid (32, 4) = (m tile, f); CTA tile 64(b) x 128(m), K chunk 32, 8 warps (4x2).
__global__ __launch_bounds__(256) void k_cleanup() {
    __shared__ __half As[64][40];     // est [b][k]
    __shared__ __half Bs[128][40];    // C   [m][k]
    __shared__ float simS[64][128];
    const int f = blockIdx.y;
    const int mtb = blockIdx.x * 128;
    const int tid = threadIdx.x, lane = tid & 31, w = tid >> 5;
    const int wm = w >> 1, wn = w & 1;
    const int mr = wm * 16, nc = wn * 64;

    float acc[8][4];
#pragma unroll
    for (int j = 0; j < 8; j++)
#pragma unroll
        for (int q = 0; q < 4; q++) acc[j][q] = 0.f;

    const __half* A = g_est[1] + (size_t)f * B_ * D_;
    const __half* C = g_Ch + (size_t)f * M_ * D_;
    const int rb = tid >> 2, kga = (tid & 3) * 8;
    const int nb = tid >> 1, kgb = (tid & 1) * 16;

    for (int k0 = 0; k0 < D_; k0 += 32) {
        *(uint4*)&As[rb][kga] = *(const uint4*)(A + (size_t)rb * D_ + k0 + kga);
        *(uint4*)&Bs[nb][kgb]     = *(const uint4*)(C + (size_t)(mtb + nb) * D_ + k0 + kgb);
        *(uint4*)&Bs[nb][kgb + 8] = *(const uint4*)(C + (size_t)(mtb + nb) * D_ + k0 + kgb + 8);
        __syncthreads();
#pragma unroll
        for (int kk = 0; kk < 2; kk++) {
            const int c = kk * 16 + (lane & 3) * 2;
            unsigned a[4];
            int r = mr + (lane >> 2);
            a[0] = *(const unsigned*)&As[r][c];
            a[1] = *(const unsigned*)&As[r + 8][c];
            a[2] = *(const unsigned*)&As[r][c + 8];
            a[3] = *(const unsigned*)&As[r + 8][c + 8];
#pragma unroll
            for (int j = 0; j < 8; j++) {
                int n = nc + j * 8 + (lane >> 2);
                unsigned b0 = *(const unsigned*)&Bs[n][c];
                unsigned b1 = *(const unsigned*)&Bs[n][c + 8];
                mma16816(acc[j], a, b0, b1);
            }
        }
        __syncthreads();
    }

#pragma unroll
    for (int j = 0; j < 8; j++) {
        int col = nc + j * 8 + (lane & 3) * 2;
        int r0 = mr + (lane >> 2);
        simS[r0][col] = acc[j][0];
        simS[r0][col + 1] = acc[j][1];
        simS[r0 + 8][col] = acc[j][2];
        simS[r0 + 8][col + 1] = acc[j][3];
    }
    __syncthreads();

    // per-row argmax of |sim| with first-index tie-break: key = (|sim|<<12) | (4095-m)
    const int b = tid >> 2, seg = tid & 3;
    int best = -1;
#pragma unroll
    for (int q = 0; q < 32; q++) {
        int cloc = seg * 32 + q;
        int v = (int)fabsf(simS[b][cloc]);
        int key = (v << 12) | (4095 - (mtb + cloc));
        best = max(best, key);
    }
    best = max(best, __shfl_down_sync(0xffffffffu, best, 2, 4));
    best = max(best, __shfl_down_sync(0xffffffffu, best, 1, 4));
    if ((lane & 3) == 0) atomicMax(&g_amax[b * F_ + f], best);
}

// ---------------- finalize outputs ----------------
// layout (float32): [outcome (B*F)] [est (B*F*D)] [iters] [conv]
__global__ __launch_bounds__(256) void k_final(float* out, int out_size) {
    int tid = blockIdx.x * blockDim.x + threadIdx.x;
    int stride = gridDim.x * blockDim.x;
    for (int i = tid; i < B_ * F_; i += stride)
        if (i < out_size) out[i] = (float)(4095 - (g_amax[i] & 4095));
    for (int i = tid; i < B_ * F_ * D_; i += stride) {
        int o = B_ * F_ + i;
        if (o < out_size) {
            int b = i / (F_ * D_);
            int f = (i / D_) % F_;
            int d = i % D_;
            out[o] = __half2float(g_est[1][(f * B_ + b) * D_ + d]);
        }
    }
    if (blockIdx.x == 0 && threadIdx.x == 0) {
        int iters = 0, conv = 0;
        for (int i = 0; i < ITERS_; i++) {
            if (!conv) iters++;
            if (g_diff[i] == 0) conv = 1;
        }
        int o = B_ * F_ + B_ * F_ * D_;
        if (o < out_size) out[o] = (float)iters;
        if (o + 1 < out_size) out[o + 1] = (float)conv;
    }
}

extern "C" void kernel_launch(void* const* d_in, const int* in_sizes, int n_in,
                              void* d_out, int out_size) {
    const float* inp = (const float*)d_in[0];
    const float* ie  = (const float*)d_in[1];
    const float* cb  = (const float*)d_in[2];

    k_convert_cb<<<1024, 256>>>((const float4*)cb);
    k_init<<<512, 256>>>(inp, ie);
    k_gram<<<dim3(8, 8, 4), 256>>>();
    for (int it = 0; it < ITERS_; ++it) {
        k_newest<<<128, 256>>>(it & 1);
        k_iter<<<dim3(16, 4), 256>>>(it & 1, it);
    }
    k_cleanup<<<dim3(32, 4), 256>>>();
    k_final<<<256, 256>>>((float*)d_out, out_size);
}

// round 2
// speedup vs baseline: 1.3723x; 1.3723x over previous
#include <cuda_runtime.h>
#include <cuda_fp16.h>
#include <cstdint>

#define B_ 64
#define F_ 4
#define M_ 4096
#define D_ 1024
#define ITERS_ 15
#define NCTA_ 64

// ---------------- device scratch ----------------
__device__ __half g_Ch[F_ * M_ * D_];      // codebooks fp16 +-1, [f][m][d]
__device__ __half g_G[F_ * D_ * D_];       // (C^T C)/2 fp16, [f][d1][d2]
__device__ __half g_est[2][F_ * B_ * D_];  // ping-pong estimates, [f][b][d]
__device__ __half g_ne[F_ * B_ * D_];      // unbound estimates, [f][b][d]
__device__ __half g_inp[B_ * D_];          // input +-1
__device__ int    g_diff[ITERS_];
__device__ int    g_amax[B_ * F_];
__device__ unsigned g_count;

__device__ __forceinline__ __half sgnh(float x) {
    return __float2half(x >= 0.f ? 1.f : -1.f);
}

__device__ __forceinline__ void mma16816(float* c, const unsigned* a, unsigned b0, unsigned b1) {
    asm volatile(
        "mma.sync.aligned.m16n8k16.row.col.f32.f16.f16.f32 "
        "{%0,%1,%2,%3}, {%4,%5,%6,%7}, {%8,%9}, {%0,%1,%2,%3};\n"
        : "+f"(c[0]), "+f"(c[1]), "+f"(c[2]), "+f"(c[3])
        : "r"(a[0]), "r"(a[1]), "r"(a[2]), "r"(a[3]), "r"(b0), "r"(b1));
}

__device__ __forceinline__ void ldsm4t(unsigned& r0, unsigned& r1, unsigned& r2, unsigned& r3,
                                       unsigned addr) {
    asm volatile("ldmatrix.sync.aligned.m8n8.x4.trans.shared.b16 {%0,%1,%2,%3}, [%4];\n"
                 : "=r"(r0), "=r"(r1), "=r"(r2), "=r"(r3)
                 : "r"(addr));
}

__device__ __forceinline__ unsigned sptr(const void* p) {
    return (unsigned)__cvta_generic_to_shared(p);
}

#define CP_ASYNC16(s, g) \
    asm volatile("cp.async.ca.shared.global [%0], [%1], 16;\n" ::"r"(s), "l"(g))
#define CP_COMMIT asm volatile("cp.async.commit_group;\n")
#define CP_WAIT(n) asm volatile("cp.async.wait_group %0;\n" ::"n"(n))

// software global barrier (one CTA per SM; thread0 fence invalidates L1D)
__device__ __forceinline__ void gbar(unsigned target) {
    __syncthreads();
    if (threadIdx.x == 0) {
        __threadfence();
        atomicAdd(&g_count, 1u);
        while (*((volatile unsigned*)&g_count) < target) {}
        __threadfence();
    }
    __syncthreads();
}

// ---------------- prep: convert codebooks + init state ----------------
__global__ __launch_bounds__(256) void k_prep(const float4* cb, const float* inp, const float* ie) {
    int tid = blockIdx.x * blockDim.x + threadIdx.x;
    int stride = gridDim.x * blockDim.x;
    const int n = F_ * M_ * D_ / 4;
    __half2* outc = reinterpret_cast<__half2*>(g_Ch);
    for (int i = tid; i < n; i += stride) {
        float4 v = cb[i];
        outc[2 * i] = __halves2half2(sgnh(v.x), sgnh(v.y));
        outc[2 * i + 1] = __halves2half2(sgnh(v.z), sgnh(v.w));
    }
    for (int i = tid; i < B_ * D_; i += stride) g_inp[i] = sgnh(inp[i]);
    for (int i = tid; i < B_ * F_ * D_; i += stride) {
        int b = i / (F_ * D_);
        int f = (i / D_) % F_;
        int d = i % D_;
        g_est[0][(f * B_ + b) * D_ + d] = sgnh(ie[i]);
    }
    if (tid < ITERS_) g_diff[tid] = 0;
    if (tid == 0) g_count = 0;
    for (int i = tid; i < B_ * F_; i += stride) g_amax[i] = -1;
}

// ---------------- Gram: G = (C^T C)/2, upper-tri tiles + mirror ----------------
#define GK 32
#define GPAD 136
__global__ __launch_bounds__(256, 1) void k_gram() {
    __shared__ __align__(16) __half S[2][2][GK][GPAD];  // [buf][A/B][k][d]
    int idx = blockIdx.x;
    const int f = blockIdx.y;
    int ti = 0;
    while (idx >= 8 - ti) { idx -= 8 - ti; ti++; }
    const int tj = ti + idx;
    const int d1b = ti * 128, d2b = tj * 128;
    const __half* C = g_Ch + (size_t)f * M_ * D_;
    const int tid = threadIdx.x, lane = tid & 31, w = tid >> 5;
    const int wm = w >> 2, wn = w & 3;
    const int mr = wm * 64, nc = wn * 32;

    float acc[4][4][4];
#pragma unroll
    for (int i = 0; i < 4; i++)
#pragma unroll
        for (int j = 0; j < 4; j++)
#pragma unroll
            for (int q = 0; q < 4; q++) acc[i][j][q] = 0.f;

    const int kr = tid >> 3, cq = (tid & 7) * 16;

    // prologue load chunk 0
    {
        const __half* src = C + (size_t)kr * D_;
        CP_ASYNC16(sptr(&S[0][0][kr][cq]), src + d1b + cq);
        CP_ASYNC16(sptr(&S[0][0][kr][cq + 8]), src + d1b + cq + 8);
        CP_ASYNC16(sptr(&S[0][1][kr][cq]), src + d2b + cq);
        CP_ASYNC16(sptr(&S[0][1][kr][cq + 8]), src + d2b + cq + 8);
        CP_COMMIT;
    }

    const int NCH = M_ / GK;  // 128
    for (int c = 0; c < NCH; c++) {
        const int buf = c & 1;
        if (c + 1 < NCH) {
            const __half* src = C + (size_t)(c + 1) * GK * D_ + (size_t)kr * D_;
            CP_ASYNC16(sptr(&S[buf ^ 1][0][kr][cq]), src + d1b + cq);
            CP_ASYNC16(sptr(&S[buf ^ 1][0][kr][cq + 8]), src + d1b + cq + 8);
            CP_ASYNC16(sptr(&S[buf ^ 1][1][kr][cq]), src + d2b + cq);
            CP_ASYNC16(sptr(&S[buf ^ 1][1][kr][cq + 8]), src + d2b + cq + 8);
            CP_COMMIT;
            CP_WAIT(1);
        } else {
            CP_WAIT(0);
        }
        __syncthreads();

#pragma unroll
        for (int kb = 0; kb < GK; kb += 16) {
            const int o = lane >> 3, r = lane & 7;
            unsigned a[4][4], bb[4][2];
            const int rowA = kb + ((o & 2) ? 8 : 0) + r;
#pragma unroll
            for (int i = 0; i < 4; i++) {
                const int col = mr + i * 16 + ((o & 1) ? 8 : 0);
                ldsm4t(a[i][0], a[i][1], a[i][2], a[i][3], sptr(&S[buf][0][rowA][col]));
            }
            const int rowB = kb + ((o & 1) ? 8 : 0) + r;
#pragma unroll
            for (int jp = 0; jp < 2; jp++) {
                const int col = nc + jp * 16 + ((o & 2) ? 8 : 0);
                unsigned r0, r1, r2, r3;
                ldsm4t(r0, r1, r2, r3, sptr(&S[buf][1][rowB][col]));
                bb[jp * 2][0] = r0; bb[jp * 2][1] = r1;
                bb[jp * 2 + 1][0] = r2; bb[jp * 2 + 1][1] = r3;
            }
#pragma unroll
            for (int i = 0; i < 4; i++)
#pragma unroll
                for (int j = 0; j < 4; j++) mma16816(acc[i][j], a[i], bb[j][0], bb[j][1]);
        }
        __syncthreads();
    }

    // epilogue: write tile + mirror
    __half* G = g_G + (size_t)f * D_ * D_;
#pragma unroll
    for (int i = 0; i < 4; i++) {
        const int r0 = d1b + mr + i * 16 + (lane >> 2);
        const int r1 = r0 + 8;
#pragma unroll
        for (int j = 0; j < 4; j++) {
            const int c0 = d2b + nc + j * 8 + (lane & 3) * 2;
            __half h0 = __float2half(acc[i][j][0] * 0.5f);
            __half h1 = __float2half(acc[i][j][1] * 0.5f);
            __half h2 = __float2half(acc[i][j][2] * 0.5f);
            __half h3 = __float2half(acc[i][j][3] * 0.5f);
            *(__half2*)(G + (size_t)r0 * D_ + c0) = __halves2half2(h0, h1);
            *(__half2*)(G + (size_t)r1 * D_ + c0) = __halves2half2(h2, h3);
            if (ti != tj) {
                G[(size_t)c0 * D_ + r0] = h0;
                G[(size_t)(c0 + 1) * D_ + r0] = h1;
                G[(size_t)c0 * D_ + r1] = h2;
                G[(size_t)(c0 + 1) * D_ + r1] = h3;
            }
        }
    }
}

// ---------------- persistent mega-kernel: 15 iterations + cleanup + final ----------------
__global__ __launch_bounds__(256) void k_mega(float* out, int out_size) {
    __shared__ __align__(16) union SM {
        struct { __half As[64][40]; __half Bs[64][40]; } l;
        struct { __half As[64][40]; __half Bs[128][40]; } c;
    } sm;
    const int tid = threadIdx.x, lane = tid & 31, w = tid >> 5;
    const int cta = blockIdx.x;
    const int f_l = cta & 3, tile = cta >> 2;
    const int d1b = tile * 64;

    unsigned phase = 0;
    int cur = 0;

    for (int it = 0; it < ITERS_; ++it) {
        // ---- phase A: ne[f][b][d] = inp*prod(est)*est[f] ----
        {
            const int n = B_ * D_ / 2;
            const __half2* inp2 = (const __half2*)g_inp;
            const __half2* e = (const __half2*)g_est[cur];
            __half2* ne = (__half2*)g_ne;
            for (int i = cta * 256 + tid; i < n; i += NCTA_ * 256) {
                __half2 e0 = e[i], e1 = e[n + i], e2 = e[2 * n + i], e3 = e[3 * n + i];
                __half2 t = __hmul2(__hmul2(__hmul2(__hmul2(inp2[i], e0), e1), e2), e3);
                ne[i] = __hmul2(t, e0);
                ne[n + i] = __hmul2(t, e1);
                ne[2 * n + i] = __hmul2(t, e2);
                ne[3 * n + i] = __hmul2(t, e3);
            }
        }
        phase++; gbar(NCTA_ * phase);

        // ---- phase B: upd = sign(G @ ne), tile 64b x 64d ----
        {
            const int wm = w >> 1, wn = w & 1;
            const int mr = wm * 16, ncw = wn * 32;
            float acc[4][4];
#pragma unroll
            for (int j = 0; j < 4; j++)
#pragma unroll
                for (int q = 0; q < 4; q++) acc[j][q] = 0.f;

            const __half* A = g_ne + (size_t)f_l * B_ * D_;
            const __half* Bm = g_G + (size_t)f_l * D_ * D_;
            const int rb = tid >> 2, kg = (tid & 3) * 8;

            for (int k0 = 0; k0 < D_; k0 += 32) {
                *(uint4*)&sm.l.As[rb][kg] = *(const uint4*)(A + (size_t)rb * D_ + k0 + kg);
                *(uint4*)&sm.l.Bs[rb][kg] = *(const uint4*)(Bm + (size_t)(d1b + rb) * D_ + k0 + kg);
                __syncthreads();
#pragma unroll
                for (int kk = 0; kk < 2; kk++) {
                    const int c = kk * 16 + (lane & 3) * 2;
                    unsigned a[4];
                    int r = mr + (lane >> 2);
                    a[0] = *(const unsigned*)&sm.l.As[r][c];
                    a[1] = *(const unsigned*)&sm.l.As[r + 8][c];
                    a[2] = *(const unsigned*)&sm.l.As[r][c + 8];
                    a[3] = *(const unsigned*)&sm.l.As[r + 8][c + 8];
#pragma unroll
                    for (int j = 0; j < 4; j++) {
                        int nn = ncw + j * 8 + (lane >> 2);
                        unsigned b0 = *(const unsigned*)&sm.l.Bs[nn][c];
                        unsigned b1 = *(const unsigned*)&sm.l.Bs[nn][c + 8];
                        mma16816(acc[j], a, b0, b1);
                    }
                }
                __syncthreads();
            }

            __half* enew = g_est[cur ^ 1] + (size_t)f_l * B_ * D_;
            const __half* eold = g_est[cur] + (size_t)f_l * B_ * D_;
            bool changed = false;
#pragma unroll
            for (int j = 0; j < 4; j++) {
                int col = d1b + ncw + j * 8 + (lane & 3) * 2;
                int r0 = mr + (lane >> 2);
#pragma unroll
                for (int hh = 0; hh < 2; hh++) {
                    int r = r0 + hh * 8;
                    __half s0 = acc[j][hh * 2] >= 0.f ? __float2half(1.f) : __float2half(-1.f);
                    __half s1 = acc[j][hh * 2 + 1] >= 0.f ? __float2half(1.f) : __float2half(-1.f);
                    __half2 old = *(const __half2*)(eold + (size_t)r * D_ + col);
                    *(__half2*)(enew + (size_t)r * D_ + col) = __halves2half2(s0, s1);
                    changed |= (__half_as_ushort(s0) != __half_as_ushort(__low2half(old)));
                    changed |= (__half_as_ushort(s1) != __half_as_ushort(__high2half(old)));
                }
            }
            unsigned mask = __ballot_sync(0xffffffffu, changed);
            if (lane == 0 && mask) atomicOr(&g_diff[it], 1);
        }
        phase++; gbar(NCTA_ * phase);
        int ch = g_diff[it];
        cur ^= 1;
        if (ch == 0) break;  // fixed point: remaining iterations are no-ops
    }

    // ---- cleanup: sim = est @ C^T, fused |.| argmax (2 units per CTA) ----
    for (int u = cta; u < 128; u += NCTA_) {
        const int fc = u & 3;
        const int mtb = (u >> 2) * 128;
        const int wm = w >> 1, wn = w & 1;
        const int mr = wm * 16, ncw = wn * 64;

        float acc[8][4];
#pragma unroll
        for (int j = 0; j < 8; j++)
#pragma unroll
            for (int q = 0; q < 4; q++) acc[j][q] = 0.f;

        const __half* A = g_est[cur] + (size_t)fc * B_ * D_;
        const __half* C = g_Ch + (size_t)fc * M_ * D_;
        const int rb = tid >> 2, kga = (tid & 3) * 8;
        const int nb = tid >> 1, kgb = (tid & 1) * 16;

        for (int k0 = 0; k0 < D_; k0 += 32) {
            *(uint4*)&sm.c.As[rb][kga] = *(const uint4*)(A + (size_t)rb * D_ + k0 + kga);
            *(uint4*)&sm.c.Bs[nb][kgb] = *(const uint4*)(C + (size_t)(mtb + nb) * D_ + k0 + kgb);
            *(uint4*)&sm.c.Bs[nb][kgb + 8] =
                *(const uint4*)(C + (size_t)(mtb + nb) * D_ + k0 + kgb + 8);
            __syncthreads();
#pragma unroll
            for (int kk = 0; kk < 2; kk++) {
                const int c = kk * 16 + (lane & 3) * 2;
                unsigned a[4];
                int r = mr + (lane >> 2);
                a[0] = *(const unsigned*)&sm.c.As[r][c];
                a[1] = *(const unsigned*)&sm.c.As[r + 8][c];
                a[2] = *(const unsigned*)&sm.c.As[r][c + 8];
                a[3] = *(const unsigned*)&sm.c.As[r + 8][c + 8];
#pragma unroll
                for (int j = 0; j < 8; j++) {
                    int nn = ncw + j * 8 + (lane >> 2);
                    unsigned b0 = *(const unsigned*)&sm.c.Bs[nn][c];
                    unsigned b1 = *(const unsigned*)&sm.c.Bs[nn][c + 8];
                    mma16816(acc[j], a, b0, b1);
                }
            }
            __syncthreads();
        }

        // per-thread argmax over the 16 m-values this thread owns, for its 2 b-rows
        const int b0 = mr + (lane >> 2);
        int best0 = -1, best1 = -1;
#pragma unroll
        for (int j = 0; j < 8; j++) {
            const int m = mtb + ncw + j * 8 + (lane & 3) * 2;
#pragma unroll
            for (int q = 0; q < 2; q++) {
                int k0i = (((int)fabsf(acc[j][q])) << 12) | (4095 - (m + q));
                int k1i = (((int)fabsf(acc[j][2 + q])) << 12) | (4095 - (m + q));
                best0 = max(best0, k0i);
                best1 = max(best1, k1i);
            }
        }
        atomicMax(&g_amax[b0 * F_ + fc], best0);
        atomicMax(&g_amax[(b0 + 8) * F_ + fc], best1);
    }
    phase++; gbar(NCTA_ * phase);

    // ---- final outputs: [outcome(256)] [est(262144)] [iters] [conv] ----
    {
        const int g = cta * 256 + tid, gs = NCTA_ * 256;
        for (int i = g; i < B_ * F_; i += gs)
            if (i < out_size) out[i] = (float)(4095 - (g_amax[i] & 4095));
        for (int i = g; i < B_ * F_ * D_; i += gs) {
            int o = B_ * F_ + i;
            if (o < out_size) {
                int b = i / (F_ * D_);
                int f = (i / D_) % F_;
                int d = i % D_;
                out[o] = __half2float(g_est[cur][(f * B_ + b) * D_ + d]);
            }
        }
        if (cta == 0 && tid == 0) {
            int iters = 0, conv = 0;
            for (int i = 0; i < ITERS_; i++) {
                if (!conv) iters++;
                if (g_diff[i] == 0) conv = 1;
            }
            int o = B_ * F_ + B_ * F_ * D_;
            if (o < out_size) out[o] = (float)iters;
            if (o + 1 < out_size) out[o + 1] = (float)conv;
        }
    }
}

extern "C" void kernel_launch(void* const* d_in, const int* in_sizes, int n_in,
                              void* d_out, int out_size) {
    const float* inp = (const float*)d_in[0];
    const float* ie  = (const float*)d_in[1];
    const float* cb  = (const float*)d_in[2];

    k_prep<<<1024, 256>>>((const float4*)cb, inp, ie);
    k_gram<<<dim3(36, 4), 256>>>();
    k_mega<<<NCTA_, 256>>>((float*)d_out, out_size);
}

// round 3
// speedup vs baseline: 1.6905x; 1.2319x over previous
#include <cuda_runtime.h>
#include <cuda_fp16.h>
#include <cstdint>

#define B_ 64
#define F_ 4
#define M_ 4096
#define D_ 1024
#define ITERS_ 15
#define NCTA_ 128
#define NHALF_ (B_ * D_ / 2)  // 32768 uint32 per factor

// ---------------- device scratch ----------------
__device__ __half g_Ch[F_ * M_ * D_];      // codebooks fp16 +-1, [f][m][d]
__device__ __half g_G[F_ * D_ * D_];       // (C^T C)/2 fp16, [f][d1][d2]
__device__ __half g_est[2][F_ * B_ * D_];  // ping-pong estimates, [f][b][d]
__device__ __half g_ne[F_ * B_ * D_];      // unbound estimates, [f][b][d]
__device__ __half g_inp[B_ * D_];          // input +-1
__device__ int    g_diff[ITERS_];
__device__ int    g_amax[B_ * F_];
__device__ unsigned g_count;

__device__ __forceinline__ __half sgnh(float x) {
    return __float2half(x >= 0.f ? 1.f : -1.f);
}

__device__ __forceinline__ void mma16816(float* c, const unsigned* a, unsigned b0, unsigned b1) {
    asm volatile(
        "mma.sync.aligned.m16n8k16.row.col.f32.f16.f16.f32 "
        "{%0,%1,%2,%3}, {%4,%5,%6,%7}, {%8,%9}, {%0,%1,%2,%3};\n"
        : "+f"(c[0]), "+f"(c[1]), "+f"(c[2]), "+f"(c[3])
        : "r"(a[0]), "r"(a[1]), "r"(a[2]), "r"(a[3]), "r"(b0), "r"(b1));
}

__device__ __forceinline__ void ldsm4(unsigned& r0, unsigned& r1, unsigned& r2, unsigned& r3,
                                      unsigned addr) {
    asm volatile("ldmatrix.sync.aligned.m8n8.x4.shared.b16 {%0,%1,%2,%3}, [%4];\n"
                 : "=r"(r0), "=r"(r1), "=r"(r2), "=r"(r3)
                 : "r"(addr));
}

__device__ __forceinline__ void ldsm4t(unsigned& r0, unsigned& r1, unsigned& r2, unsigned& r3,
                                       unsigned addr) {
    asm volatile("ldmatrix.sync.aligned.m8n8.x4.trans.shared.b16 {%0,%1,%2,%3}, [%4];\n"
                 : "=r"(r0), "=r"(r1), "=r"(r2), "=r"(r3)
                 : "r"(addr));
}

__device__ __forceinline__ unsigned sptr(const void* p) {
    return (unsigned)__cvta_generic_to_shared(p);
}

#define CP_ASYNC16(s, g) \
    asm volatile("cp.async.ca.shared.global [%0], [%1], 16;\n" ::"r"(s), "l"(g))
#define CP_COMMIT asm volatile("cp.async.commit_group;\n")
#define CP_WAIT(n) asm volatile("cp.async.wait_group %0;\n" ::"n"(n))

// software global barrier (one CTA per SM; thread0 fence invalidates L1D)
__device__ __forceinline__ void gbar(unsigned target) {
    __syncthreads();
    if (threadIdx.x == 0) {
        __threadfence();
        atomicAdd(&g_count, 1u);
        while (*((volatile unsigned*)&g_count) < target) {}
        __threadfence();
    }
    __syncthreads();
}

// ---------------- prep ----------------
__global__ __launch_bounds__(256) void k_prep(const float4* cb, const float* inp, const float* ie) {
    int tid = blockIdx.x * blockDim.x + threadIdx.x;
    int stride = gridDim.x * blockDim.x;
    const int n = F_ * M_ * D_ / 4;
    __half2* outc = reinterpret_cast<__half2*>(g_Ch);
    for (int i = tid; i < n; i += stride) {
        float4 v = cb[i];
        outc[2 * i] = __halves2half2(sgnh(v.x), sgnh(v.y));
        outc[2 * i + 1] = __halves2half2(sgnh(v.z), sgnh(v.w));
    }
    for (int i = tid; i < B_ * D_; i += stride) g_inp[i] = sgnh(inp[i]);
    for (int i = tid; i < B_ * F_ * D_; i += stride) {
        int b = i / (F_ * D_);
        int f = (i / D_) % F_;
        int d = i % D_;
        g_est[0][(f * B_ + b) * D_ + d] = sgnh(ie[i]);
    }
    if (tid < ITERS_) g_diff[tid] = 0;
    if (tid == 0) g_count = 0;
    for (int i = tid; i < B_ * F_; i += stride) g_amax[i] = -1;
}

// ---------------- Gram: G = (C^T C)/2, upper-tri tiles + mirror ----------------
#define GK 32
#define GPAD 136
__global__ __launch_bounds__(256, 1) void k_gram() {
    __shared__ __align__(16) __half S[2][2][GK][GPAD];
    int idx = blockIdx.x;
    const int f = blockIdx.y;
    int ti = 0;
    while (idx >= 8 - ti) { idx -= 8 - ti; ti++; }
    const int tj = ti + idx;
    const int d1b = ti * 128, d2b = tj * 128;
    const __half* C = g_Ch + (size_t)f * M_ * D_;
    const int tid = threadIdx.x, lane = tid & 31, w = tid >> 5;
    const int wm = w >> 2, wn = w & 3;
    const int mr = wm * 64, nc = wn * 32;

    float acc[4][4][4];
#pragma unroll
    for (int i = 0; i < 4; i++)
#pragma unroll
        for (int j = 0; j < 4; j++)
#pragma unroll
            for (int q = 0; q < 4; q++) acc[i][j][q] = 0.f;

    const int kr = tid >> 3, cq = (tid & 7) * 16;
    {
        const __half* src = C + (size_t)kr * D_;
        CP_ASYNC16(sptr(&S[0][0][kr][cq]), src + d1b + cq);
        CP_ASYNC16(sptr(&S[0][0][kr][cq + 8]), src + d1b + cq + 8);
        CP_ASYNC16(sptr(&S[0][1][kr][cq]), src + d2b + cq);
        CP_ASYNC16(sptr(&S[0][1][kr][cq + 8]), src + d2b + cq + 8);
        CP_COMMIT;
    }
    const int NCH = M_ / GK;
    for (int c = 0; c < NCH; c++) {
        const int buf = c & 1;
        if (c + 1 < NCH) {
            const __half* src = C + (size_t)(c + 1) * GK * D_ + (size_t)kr * D_;
            CP_ASYNC16(sptr(&S[buf ^ 1][0][kr][cq]), src + d1b + cq);
            CP_ASYNC16(sptr(&S[buf ^ 1][0][kr][cq + 8]), src + d1b + cq + 8);
            CP_ASYNC16(sptr(&S[buf ^ 1][1][kr][cq]), src + d2b + cq);
            CP_ASYNC16(sptr(&S[buf ^ 1][1][kr][cq + 8]), src + d2b + cq + 8);
            CP_COMMIT;
            CP_WAIT(1);
        } else {
            CP_WAIT(0);
        }
        __syncthreads();
#pragma unroll
        for (int kb = 0; kb < GK; kb += 16) {
            const int o = lane >> 3, r = lane & 7;
            unsigned a[4][4], bb[4][2];
            const int rowA = kb + ((o & 2) ? 8 : 0) + r;
#pragma unroll
            for (int i = 0; i < 4; i++) {
                const int col = mr + i * 16 + ((o & 1) ? 8 : 0);
                ldsm4t(a[i][0], a[i][1], a[i][2], a[i][3], sptr(&S[buf][0][rowA][col]));
            }
            const int rowB = kb + ((o & 1) ? 8 : 0) + r;
#pragma unroll
            for (int jp = 0; jp < 2; jp++) {
                const int col = nc + jp * 16 + ((o & 2) ? 8 : 0);
                unsigned r0, r1, r2, r3;
                ldsm4t(r0, r1, r2, r3, sptr(&S[buf][1][rowB][col]));
                bb[jp * 2][0] = r0; bb[jp * 2][1] = r1;
                bb[jp * 2 + 1][0] = r2; bb[jp * 2 + 1][1] = r3;
            }
#pragma unroll
            for (int i = 0; i < 4; i++)
#pragma unroll
                for (int j = 0; j < 4; j++) mma16816(acc[i][j], a[i], bb[j][0], bb[j][1]);
        }
        __syncthreads();
    }
    __half* G = g_G + (size_t)f * D_ * D_;
#pragma unroll
    for (int i = 0; i < 4; i++) {
        const int r0 = d1b + mr + i * 16 + (lane >> 2);
        const int r1 = r0 + 8;
#pragma unroll
        for (int j = 0; j < 4; j++) {
            const int c0 = d2b + nc + j * 8 + (lane & 3) * 2;
            __half h0 = __float2half(acc[i][j][0] * 0.5f);
            __half h1 = __float2half(acc[i][j][1] * 0.5f);
            __half h2 = __float2half(acc[i][j][2] * 0.5f);
            __half h3 = __float2half(acc[i][j][3] * 0.5f);
            *(__half2*)(G + (size_t)r0 * D_ + c0) = __halves2half2(h0, h1);
            *(__half2*)(G + (size_t)r1 * D_ + c0) = __halves2half2(h2, h3);
            if (ti != tj) {
                G[(size_t)c0 * D_ + r0] = h0;
                G[(size_t)(c0 + 1) * D_ + r0] = h1;
                G[(size_t)c0 * D_ + r1] = h2;
                G[(size_t)(c0 + 1) * D_ + r1] = h3;
            }
        }
    }
}

// ---------------- persistent mega-kernel ----------------
__device__ __forceinline__ unsigned packsign(float x, float y) {
    return (x >= 0.f ? 0x3C00u : 0xBC00u) | ((y >= 0.f ? 0x3C00u : 0xBC00u) << 16);
}

__global__ __launch_bounds__(256) void k_mega(float* out, int out_size) {
    __shared__ __align__(16) union SM {
        struct { __half NE[4][64][40]; __half Gs[4][32][40]; } b;   // 30720 B
        struct { __half As[2][64][40]; __half Bs[2][128][40]; } c;  // 30720 B
    } sm;
    const int tid = threadIdx.x, lane = tid & 31, w = tid >> 5;
    const int cta = blockIdx.x;
    const int f_l = cta & 3, dt = cta >> 2;      // 32 d-tiles x 4 factors
    const int d1b = dt * 32;
    const int wb = w & 3, wd = w >> 2;           // 4 b-warps x 2 d-warps

    // epilogue coordinates (fixed per thread across iterations)
    const int er = wb * 16 + (lane >> 2);        // b row
    const int ec = d1b + wd * 16 + (lane & 3) * 2;  // d col (tile0); tile1 at +8

    // previous tile sign bits in registers (init from est[0])
    unsigned prev[4];
    {
        const __half* e0 = g_est[0] + (size_t)f_l * B_ * D_;
        prev[0] = *(const unsigned*)(e0 + (size_t)er * D_ + ec);
        prev[1] = *(const unsigned*)(e0 + (size_t)(er + 8) * D_ + ec);
        prev[2] = *(const unsigned*)(e0 + (size_t)er * D_ + ec + 8);
        prev[3] = *(const unsigned*)(e0 + (size_t)(er + 8) * D_ + ec + 8);
    }

    unsigned phase = 0;
    int cur = 0;

    for (int it = 0; it < ITERS_; ++it) {
        // ---- phase A: ne_f = inp * prod_{j!=f} e_j  via XOR on packed fp16 ----
        {
            const unsigned* inp2 = (const unsigned*)g_inp;
            const unsigned* e = (const unsigned*)g_est[cur];
            unsigned* ne = (unsigned*)g_ne;
            const int i = cta * 256 + tid;  // exactly NHALF_ threads
            unsigned a0 = e[i], a1 = e[NHALF_ + i], a2 = e[2 * NHALF_ + i], a3 = e[3 * NHALF_ + i];
            unsigned X = inp2[i] ^ a0 ^ a1 ^ a2 ^ a3;  // odd count: valid +-1 pattern
            ne[i] = X ^ a0 ^ 0x3C003C00u;
            ne[NHALF_ + i] = X ^ a1 ^ 0x3C003C00u;
            ne[2 * NHALF_ + i] = X ^ a2 ^ 0x3C003C00u;
            ne[3 * NHALF_ + i] = X ^ a3 ^ 0x3C003C00u;
        }
        phase++; gbar(NCTA_ * phase);

        // ---- phase B: upd = sign(G @ ne), 64b x 32d per CTA, 4-stage pipeline ----
        {
            float acc0[4] = {0.f, 0.f, 0.f, 0.f};
            float acc1[4] = {0.f, 0.f, 0.f, 0.f};
            const __half* NEg = g_ne + (size_t)f_l * B_ * D_;
            const __half* Gg = g_G + (size_t)f_l * D_ * D_;
            const int lb = tid >> 2, seg = (tid & 3) * 8;

#define PB_ISSUE(cc)                                                                   \
    do {                                                                               \
        CP_ASYNC16(sptr(&sm.b.NE[(cc) & 3][lb][seg]), NEg + (size_t)lb * D_ + (cc) * 32 + seg); \
        if (tid < 128)                                                                 \
            CP_ASYNC16(sptr(&sm.b.Gs[(cc) & 3][lb][seg]),                              \
                       Gg + (size_t)(d1b + lb) * D_ + (cc) * 32 + seg);                \
        CP_COMMIT;                                                                     \
    } while (0)

            PB_ISSUE(0); PB_ISSUE(1); PB_ISSUE(2);
            for (int c = 0; c < 32; c++) {
                CP_WAIT(2);
                __syncthreads();
                const int buf = c & 3;
#pragma unroll
                for (int ks = 0; ks < 2; ks++) {
                    const int rowA = wb * 16 + (lane & 15);
                    const int colh = ks * 16 + (lane >> 4) * 8;
                    unsigned a[4];
                    ldsm4(a[0], a[1], a[2], a[3], sptr(&sm.b.NE[buf][rowA][colh]));
                    const int rowB = wd * 16 + (lane & 15);
                    unsigned b0, b1, b2, b3;
                    ldsm4(b0, b1, b2, b3, sptr(&sm.b.Gs[buf][rowB][colh]));
                    mma16816(acc0, a, b0, b2);
                    mma16816(acc1, a, b1, b3);
                }
                __syncthreads();
                if (c + 3 < 32) { PB_ISSUE(c + 3); } else { CP_COMMIT; }
            }
#undef PB_ISSUE

            // epilogue: sign, compare with register-held prev, store
            __half* enew = g_est[cur ^ 1] + (size_t)f_l * B_ * D_;
            unsigned s[4];
            s[0] = packsign(acc0[0], acc0[1]);
            s[1] = packsign(acc0[2], acc0[3]);
            s[2] = packsign(acc1[0], acc1[1]);
            s[3] = packsign(acc1[2], acc1[3]);
            *(unsigned*)(enew + (size_t)er * D_ + ec) = s[0];
            *(unsigned*)(enew + (size_t)(er + 8) * D_ + ec) = s[1];
            *(unsigned*)(enew + (size_t)er * D_ + ec + 8) = s[2];
            *(unsigned*)(enew + (size_t)(er + 8) * D_ + ec + 8) = s[3];
            bool changed = (s[0] != prev[0]) | (s[1] != prev[1]) | (s[2] != prev[2]) |
                           (s[3] != prev[3]);
            prev[0] = s[0]; prev[1] = s[1]; prev[2] = s[2]; prev[3] = s[3];
            unsigned mask = __ballot_sync(0xffffffffu, changed);
            if (lane == 0 && mask) atomicOr(&g_diff[it], 1);
        }
        phase++; gbar(NCTA_ * phase);
        int ch = g_diff[it];
        cur ^= 1;
        if (ch == 0) break;  // fixed point: remaining iterations are no-ops
    }

    // ---- cleanup: sim = est @ C^T, 64b x 128m per CTA, fused |.| argmax ----
    {
        const int fc = f_l;
        const int mtb = dt * 128;
        const int wd2 = w >> 2;  // 0..1, 64 m each
        float acc[8][4];
#pragma unroll
        for (int j = 0; j < 8; j++)
#pragma unroll
            for (int q = 0; q < 4; q++) acc[j][q] = 0.f;

        const __half* A = g_est[cur] + (size_t)fc * B_ * D_;
        const __half* C = g_Ch + (size_t)fc * M_ * D_;
        const int lb = tid >> 2, seg = (tid & 3) * 8;
        const int rb2 = tid >> 1, segb = (tid & 1) * 16;

#define CL_ISSUE(cc)                                                                      \
    do {                                                                                  \
        CP_ASYNC16(sptr(&sm.c.As[(cc) & 1][lb][seg]), A + (size_t)lb * D_ + (cc) * 32 + seg); \
        CP_ASYNC16(sptr(&sm.c.Bs[(cc) & 1][rb2][segb]),                                   \
                   C + (size_t)(mtb + rb2) * D_ + (cc) * 32 + segb);                      \
        CP_ASYNC16(sptr(&sm.c.Bs[(cc) & 1][rb2][segb + 8]),                               \
                   C + (size_t)(mtb + rb2) * D_ + (cc) * 32 + segb + 8);                  \
        CP_COMMIT;                                                                        \
    } while (0)

        CL_ISSUE(0);
        for (int c = 0; c < 32; c++) {
            const int buf = c & 1;
            if (c + 1 < 32) { CL_ISSUE(c + 1); CP_WAIT(1); } else { CP_WAIT(0); }
            __syncthreads();
#pragma unroll
            for (int ks = 0; ks < 2; ks++) {
                const int rowA = wb * 16 + (lane & 15);
                const int colh = ks * 16 + (lane >> 4) * 8;
                unsigned a[4];
                ldsm4(a[0], a[1], a[2], a[3], sptr(&sm.c.As[buf][rowA][colh]));
#pragma unroll
                for (int jj = 0; jj < 4; jj++) {
                    const int rowB = wd2 * 64 + jj * 16 + (lane & 15);
                    unsigned b0, b1, b2, b3;
                    ldsm4(b0, b1, b2, b3, sptr(&sm.c.Bs[buf][rowB][colh]));
                    mma16816(acc[2 * jj], a, b0, b2);
                    mma16816(acc[2 * jj + 1], a, b1, b3);
                }
            }
            __syncthreads();
        }
#undef CL_ISSUE

        int best0 = -1, best1 = -1;
#pragma unroll
        for (int jj = 0; jj < 4; jj++) {
#pragma unroll
            for (int t = 0; t < 2; t++) {
                const int m0 = mtb + wd2 * 64 + jj * 16 + t * 8 + (lane & 3) * 2;
                const float* ac = acc[2 * jj + t];
#pragma unroll
                for (int q = 0; q < 2; q++) {
                    best0 = max(best0, (((int)fabsf(ac[q])) << 12) | (4095 - (m0 + q)));
                    best1 = max(best1, (((int)fabsf(ac[2 + q])) << 12) | (4095 - (m0 + q)));
                }
            }
        }
        atomicMax(&g_amax[er * F_ + fc], best0);
        atomicMax(&g_amax[(er + 8) * F_ + fc], best1);
    }
    phase++; gbar(NCTA_ * phase);

    // ---- final outputs: [outcome(256)] [est(262144)] [iters] [conv] ----
    {
        const int g = cta * 256 + tid, gs = NCTA_ * 256;
        for (int i = g; i < B_ * F_; i += gs)
            if (i < out_size) out[i] = (float)(4095 - (g_amax[i] & 4095));
        for (int i = g; i < B_ * F_ * D_; i += gs) {
            int o = B_ * F_ + i;
            if (o < out_size) {
                int b = i / (F_ * D_);
                int f = (i / D_) % F_;
                int d = i % D_;
                out[o] = __half2float(g_est[cur][(f * B_ + b) * D_ + d]);
            }
        }
        if (cta == 0 && tid == 0) {
            int iters = 0, conv = 0;
            for (int i = 0; i < ITERS_; i++) {
                if (!conv) iters++;
                if (g_diff[i] == 0) conv = 1;
            }
            int o = B_ * F_ + B_ * F_ * D_;
            if (o < out_size) out[o] = (float)iters;
            if (o + 1 < out_size) out[o + 1] = (float)conv;
        }
    }
}

extern "C" void kernel_launch(void* const* d_in, const int* in_sizes, int n_in,
                              void* d_out, int out_size) {
    const float* inp = (const float*)d_in[0];
    const float* ie  = (const float*)d_in[1];
    const float* cb  = (const float*)d_in[2];

    k_prep<<<1024, 256>>>((const float4*)cb, inp, ie);
    k_gram<<<dim3(36, 4), 256>>>();
    k_mega<<<NCTA_, 256>>>((float*)d_out, out_size);
}

// round 9
// speedup vs baseline: 1.7966x; 1.0628x over previous
#include <cuda_runtime.h>
#include <cuda_fp16.h>
#include <cstdint>

#define B_ 64
#define F_ 4
#define M_ 4096
#define D_ 1024
#define ITERS_ 15
#define NCTA_ 128
#define NHALF_ (B_ * D_ / 2)

// ---------------- device scratch ----------------
__device__ __half  g_Ch[F_ * M_ * D_];      // codebooks fp16 +-1, [f][m][d]
__device__ int8_t  g_Cti[F_ * D_ * M_];     // transposed int8 codebooks, [f][d][m]
__device__ __half  g_G[F_ * D_ * D_];       // (C^T C)/2 fp16, [f][d1][d2]
__device__ __half  g_est[2][F_ * B_ * D_];  // ping-pong estimates, [f][b][d]
__device__ __half  g_ne[F_ * B_ * D_];      // unbound estimates, [f][b][d]
__device__ __half  g_inp[B_ * D_];          // input +-1
__device__ int     g_diff[ITERS_];
__device__ int     g_amax[B_ * F_];
__device__ unsigned g_count;

__device__ __forceinline__ __half sgnh(float x) {
    return __float2half(x >= 0.f ? 1.f : -1.f);
}

__device__ __forceinline__ void mma16816(float* c, const unsigned* a, unsigned b0, unsigned b1) {
    asm volatile(
        "mma.sync.aligned.m16n8k16.row.col.f32.f16.f16.f32 "
        "{%0,%1,%2,%3}, {%4,%5,%6,%7}, {%8,%9}, {%0,%1,%2,%3};\n"
        : "+f"(c[0]), "+f"(c[1]), "+f"(c[2]), "+f"(c[3])
        : "r"(a[0]), "r"(a[1]), "r"(a[2]), "r"(a[3]), "r"(b0), "r"(b1));
}

__device__ __forceinline__ void imma16832(int* c, const unsigned* a, unsigned b0, unsigned b1) {
    asm volatile(
        "mma.sync.aligned.m16n8k32.row.col.s32.s8.s8.s32 "
        "{%0,%1,%2,%3}, {%4,%5,%6,%7}, {%8,%9}, {%0,%1,%2,%3};\n"
        : "+r"(c[0]), "+r"(c[1]), "+r"(c[2]), "+r"(c[3])
        : "r"(a[0]), "r"(a[1]), "r"(a[2]), "r"(a[3]), "r"(b0), "r"(b1));
}

__device__ __forceinline__ void ldsm4(unsigned& r0, unsigned& r1, unsigned& r2, unsigned& r3,
                                      unsigned addr) {
    asm volatile("ldmatrix.sync.aligned.m8n8.x4.shared.b16 {%0,%1,%2,%3}, [%4];\n"
                 : "=r"(r0), "=r"(r1), "=r"(r2), "=r"(r3)
                 : "r"(addr));
}

__device__ __forceinline__ unsigned sptr(const void* p) {
    return (unsigned)__cvta_generic_to_shared(p);
}

#define CP_ASYNC16(s, g) \
    asm volatile("cp.async.ca.shared.global [%0], [%1], 16;\n" ::"r"(s), "l"(g))
#define CP_COMMIT asm volatile("cp.async.commit_group;\n")
#define CP_WAIT(n) asm volatile("cp.async.wait_group %0;\n" ::"n"(n))

// software global barrier
__device__ __forceinline__ void gbar(unsigned target) {
    __syncthreads();
    if (threadIdx.x == 0) {
        __threadfence();
        atomicAdd(&g_count, 1u);
        while (*((volatile unsigned*)&g_count) < target) {}
        __threadfence();
    }
    __syncthreads();
}

// ---------------- prep ----------------
__global__ __launch_bounds__(256) void k_prep(const float4* cb, const float* inp, const float* ie) {
    int tid = blockIdx.x * blockDim.x + threadIdx.x;
    int stride = gridDim.x * blockDim.x;
    const int n = F_ * M_ * D_ / 4;
    __half2* outc = reinterpret_cast<__half2*>(g_Ch);
    for (int i = tid; i < n; i += stride) {
        float4 v = cb[i];
        outc[2 * i] = __halves2half2(sgnh(v.x), sgnh(v.y));
        outc[2 * i + 1] = __halves2half2(sgnh(v.z), sgnh(v.w));
    }
    for (int i = tid; i < B_ * D_; i += stride) g_inp[i] = sgnh(inp[i]);
    for (int i = tid; i < B_ * F_ * D_; i += stride) {
        int b = i / (F_ * D_);
        int f = (i / D_) % F_;
        int d = i % D_;
        g_est[0][(f * B_ + b) * D_ + d] = sgnh(ie[i]);
    }
    if (tid < ITERS_) g_diff[tid] = 0;
    if (tid == 0) g_count = 0;
    for (int i = tid; i < B_ * F_; i += stride) g_amax[i] = -1;
}

// ---------------- transpose + int8: Cti[f][d][m] = sign8(Ch[f][m][d]) ----------------
__global__ __launch_bounds__(256) void k_trans8() {
    __shared__ __half T[64][72];
    const int mt = blockIdx.x * 64, dt = blockIdx.y * 64, f = blockIdx.z;
    const int tid = threadIdx.x;
    const __half* src = g_Ch + (size_t)f * M_ * D_;
    int8_t* dst = g_Cti + (size_t)f * D_ * M_;
#pragma unroll
    for (int q = 0; q < 2; q++) {
        int o = tid * 2 + q;
        int r = o >> 3, seg = o & 7;
        *(uint4*)&T[r][seg * 8] = *(const uint4*)(src + (size_t)(mt + r) * D_ + dt + seg * 8);
    }
    __syncthreads();
#pragma unroll
    for (int q = 0; q < 2; q++) {
        int o = tid * 2 + q;
        int r = o >> 3, seg = o & 7;
        int8_t tmp[8];
#pragma unroll
        for (int j = 0; j < 8; j++)
            tmp[j] = (__half_as_ushort(T[seg * 8 + j][r]) & 0x8000) ? (int8_t)-1 : (int8_t)1;
        *(uint2*)(dst + (size_t)(dt + r) * M_ + mt + seg * 8) = *(uint2*)tmp;
    }
}

// ---------------- Gram via int8 IMMA: G = (C^T C)/2 ----------------
// grid (36, 4): upper-tri 128x128 tiles + mirror. K = 4096 int8, chunks of 64.
#define G3_PAD 80
__global__ __launch_bounds__(256) void k_gram3() {
    __shared__ __align__(16) int8_t SA[2][128][G3_PAD];
    __shared__ __align__(16) int8_t SB[2][128][G3_PAD];
    int idx = blockIdx.x;
    const int f = blockIdx.y;
    int ti = 0;
    while (idx >= 8 - ti) { idx -= 8 - ti; ti++; }
    const int tj = ti + idx;
    const int d1b = ti * 128, d2b = tj * 128;
    const int8_t* Ct = g_Cti + (size_t)f * D_ * M_;
    const int tid = threadIdx.x, lane = tid & 31, w = tid >> 5;
    const int wm = w >> 2, wn = w & 3;  // 2 x 4 warps
    const int mr = wm * 64, nc = wn * 32;

    int acc[4][4][4];
#pragma unroll
    for (int i = 0; i < 4; i++)
#pragma unroll
        for (int j = 0; j < 4; j++)
#pragma unroll
            for (int q = 0; q < 4; q++) acc[i][j][q] = 0;

    const int r = tid & 127, op = tid >> 7;  // 128 threads load A, 128 load B
    const int8_t* srcrow = Ct + (size_t)((op ? d2b : d1b) + r) * M_;

#define G3_LOAD(cc)                                                                   \
    do {                                                                              \
        unsigned sb = op ? sptr(&SB[(cc) & 1][r][0]) : sptr(&SA[(cc) & 1][r][0]);     \
        const int8_t* s = srcrow + (cc) * 64;                                         \
        CP_ASYNC16(sb, s);                                                            \
        CP_ASYNC16(sb + 16, s + 16);                                                  \
        CP_ASYNC16(sb + 32, s + 32);                                                  \
        CP_ASYNC16(sb + 48, s + 48);                                                  \
        CP_COMMIT;                                                                    \
    } while (0)

    G3_LOAD(0);
    const int NCH = M_ / 64;  // 64 chunks
    for (int c = 0; c < NCH; c++) {
        if (c + 1 < NCH) { G3_LOAD(c + 1); CP_WAIT(1); } else { CP_WAIT(0); }
        __syncthreads();
        const int buf = c & 1;
#pragma unroll
        for (int ks = 0; ks < 2; ks++) {
            const int mg = lane >> 3, lr = lane & 7;
            unsigned a[4][4], bb[4][2];
            // A: matrix0=rows0-7/b0-15, m1=rows8-15/b0-15, m2=rows0-7/b16-31, m3=rows8-15/b16-31
            const int rowA = ((mg & 1) ? 8 : 0) + lr;
            const int bofA = ks * 32 + ((mg & 2) ? 16 : 0);
#pragma unroll
            for (int i = 0; i < 4; i++)
                ldsm4(a[i][0], a[i][1], a[i][2], a[i][3],
                      sptr(&SA[buf][mr + i * 16 + rowA][bofA]));
            // B: m0=n0-7/b0-15, m1=n0-7/b16-31, m2=n8-15/b0-15, m3=n8-15/b16-31
            const int rowB = ((mg & 2) ? 8 : 0) + lr;
            const int bofB = ks * 32 + ((mg & 1) ? 16 : 0);
#pragma unroll
            for (int jp = 0; jp < 2; jp++) {
                unsigned r0, r1, r2, r3;
                ldsm4(r0, r1, r2, r3, sptr(&SB[buf][nc + jp * 16 + rowB][bofB]));
                bb[jp * 2][0] = r0; bb[jp * 2][1] = r1;
                bb[jp * 2 + 1][0] = r2; bb[jp * 2 + 1][1] = r3;
            }
#pragma unroll
            for (int i = 0; i < 4; i++)
#pragma unroll
                for (int j = 0; j < 4; j++) imma16832(acc[i][j], a[i], bb[j][0], bb[j][1]);
        }
        __syncthreads();
    }
#undef G3_LOAD

    // epilogue: G = acc/2 (exact in fp16), mirror for off-diagonal tiles
    __half* G = g_G + (size_t)f * D_ * D_;
#pragma unroll
    for (int i = 0; i < 4; i++) {
        const int r0 = d1b + mr + i * 16 + (lane >> 2);
        const int r1 = r0 + 8;
#pragma unroll
        for (int j = 0; j < 4; j++) {
            const int c0 = d2b + nc + j * 8 + (lane & 3) * 2;
            __half h0 = __float2half((float)acc[i][j][0] * 0.5f);
            __half h1 = __float2half((float)acc[i][j][1] * 0.5f);
            __half h2 = __float2half((float)acc[i][j][2] * 0.5f);
            __half h3 = __float2half((float)acc[i][j][3] * 0.5f);
            *(__half2*)(G + (size_t)r0 * D_ + c0) = __halves2half2(h0, h1);
            *(__half2*)(G + (size_t)r1 * D_ + c0) = __halves2half2(h2, h3);
            if (ti != tj) {
                G[(size_t)c0 * D_ + r0] = h0;
                G[(size_t)(c0 + 1) * D_ + r0] = h1;
                G[(size_t)c0 * D_ + r1] = h2;
                G[(size_t)(c0 + 1) * D_ + r1] = h3;
            }
        }
    }
}

// ---------------- persistent mega-kernel ----------------
__device__ __forceinline__ unsigned packsign(float x, float y) {
    return (x >= 0.f ? 0x3C00u : 0xBC00u) | ((y >= 0.f ? 0x3C00u : 0xBC00u) << 16);
}

__global__ __launch_bounds__(256) void k_mega(float* out, int out_size) {
    __shared__ __align__(16) union SM {
        struct { __half NE[4][64][40]; __half Gs[4][32][40]; } b;
        struct { __half As[3][64][40]; __half Bs[3][128][40]; } c;
    } sm;
    const int tid = threadIdx.x, lane = tid & 31, w = tid >> 5;
    const int cta = blockIdx.x;
    const int f_l = cta & 3, dt = cta >> 2;
    const int d1b = dt * 32;
    const int wb = w & 3, wd = w >> 2;

    const int er = wb * 16 + (lane >> 2);
    const int ec = d1b + wd * 16 + (lane & 3) * 2;

    unsigned prev[4];
    {
        const __half* e0 = g_est[0] + (size_t)f_l * B_ * D_;
        prev[0] = *(const unsigned*)(e0 + (size_t)er * D_ + ec);
        prev[1] = *(const unsigned*)(e0 + (size_t)(er + 8) * D_ + ec);
        prev[2] = *(const unsigned*)(e0 + (size_t)er * D_ + ec + 8);
        prev[3] = *(const unsigned*)(e0 + (size_t)(er + 8) * D_ + ec + 8);
    }

    unsigned phase = 0;
    int cur = 0;

    for (int it = 0; it < ITERS_; ++it) {
        // ---- phase A: XOR unbind ----
        {
            const unsigned* inp2 = (const unsigned*)g_inp;
            const unsigned* e = (const unsigned*)g_est[cur];
            unsigned* ne = (unsigned*)g_ne;
            const int i = cta * 256 + tid;
            unsigned a0 = e[i], a1 = e[NHALF_ + i], a2 = e[2 * NHALF_ + i], a3 = e[3 * NHALF_ + i];
            unsigned X = inp2[i] ^ a0 ^ a1 ^ a2 ^ a3;
            ne[i] = X ^ a0 ^ 0x3C003C00u;
            ne[NHALF_ + i] = X ^ a1 ^ 0x3C003C00u;
            ne[2 * NHALF_ + i] = X ^ a2 ^ 0x3C003C00u;
            ne[3 * NHALF_ + i] = X ^ a3 ^ 0x3C003C00u;
        }
        phase++; gbar(NCTA_ * phase);

        // ---- phase B: upd = sign(G @ ne), 64b x 32d, 4-stage single-sync pipeline ----
        {
            float acc0[4] = {0.f, 0.f, 0.f, 0.f};
            float acc1[4] = {0.f, 0.f, 0.f, 0.f};
            const __half* NEg = g_ne + (size_t)f_l * B_ * D_;
            const __half* Gg = g_G + (size_t)f_l * D_ * D_;
            const int lb = tid >> 2, seg = (tid & 3) * 8;

#define PB_ISSUE(cc)                                                                   \
    do {                                                                               \
        CP_ASYNC16(sptr(&sm.b.NE[(cc) & 3][lb][seg]), NEg + (size_t)lb * D_ + (cc) * 32 + seg); \
        if (tid < 128)                                                                 \
            CP_ASYNC16(sptr(&sm.b.Gs[(cc) & 3][lb][seg]),                              \
                       Gg + (size_t)(d1b + lb) * D_ + (cc) * 32 + seg);                \
        CP_COMMIT;                                                                     \
    } while (0)

            PB_ISSUE(0); PB_ISSUE(1); PB_ISSUE(2);
            for (int c = 0; c < 32; c++) {
                CP_WAIT(2);
                __syncthreads();
                const int buf = c & 3;
#pragma unroll
                for (int ks = 0; ks < 2; ks++) {
                    const int rowA = wb * 16 + (lane & 15);
                    const int colh = ks * 16 + (lane >> 4) * 8;
                    unsigned a[4];
                    ldsm4(a[0], a[1], a[2], a[3], sptr(&sm.b.NE[buf][rowA][colh]));
                    const int rowB = wd * 16 + (lane & 15);
                    unsigned b0, b1, b2, b3;
                    ldsm4(b0, b1, b2, b3, sptr(&sm.b.Gs[buf][rowB][colh]));
                    mma16816(acc0, a, b0, b2);
                    mma16816(acc1, a, b1, b3);
                }
                if (c + 3 < 32) { PB_ISSUE(c + 3); } else { CP_COMMIT; }
            }
#undef PB_ISSUE

            __half* enew = g_est[cur ^ 1] + (size_t)f_l * B_ * D_;
            unsigned s[4];
            s[0] = packsign(acc0[0], acc0[1]);
            s[1] = packsign(acc0[2], acc0[3]);
            s[2] = packsign(acc1[0], acc1[1]);
            s[3] = packsign(acc1[2], acc1[3]);
            *(unsigned*)(enew + (size_t)er * D_ + ec) = s[0];
            *(unsigned*)(enew + (size_t)(er + 8) * D_ + ec) = s[1];
            *(unsigned*)(enew + (size_t)er * D_ + ec + 8) = s[2];
            *(unsigned*)(enew + (size_t)(er + 8) * D_ + ec + 8) = s[3];
            bool changed = (s[0] != prev[0]) | (s[1] != prev[1]) | (s[2] != prev[2]) |
                           (s[3] != prev[3]);
            prev[0] = s[0]; prev[1] = s[1]; prev[2] = s[2]; prev[3] = s[3];
            unsigned mask = __ballot_sync(0xffffffffu, changed);
            if (lane == 0 && mask) atomicOr(&g_diff[it], 1);
        }
        phase++; gbar(NCTA_ * phase);
        int ch = g_diff[it];
        cur ^= 1;
        if (ch == 0) break;
    }

    // ---- cleanup: sim = est @ C^T, 64b x 128m, 3-stage single-sync pipeline ----
    {
        const int fc = f_l;
        const int mtb = dt * 128;
        const int wd2 = w >> 2;
        float acc[8][4];
#pragma unroll
        for (int j = 0; j < 8; j++)
#pragma unroll
            for (int q = 0; q < 4; q++) acc[j][q] = 0.f;

        const __half* A = g_est[cur] + (size_t)fc * B_ * D_;
        const __half* C = g_Ch + (size_t)fc * M_ * D_;
        const int lb = tid >> 2, seg = (tid & 3) * 8;
        const int rb2 = tid >> 1, segb = (tid & 1) * 16;

#define CL_ISSUE(cc)                                                                      \
    do {                                                                                  \
        CP_ASYNC16(sptr(&sm.c.As[(cc) % 3][lb][seg]), A + (size_t)lb * D_ + (cc) * 32 + seg); \
        CP_ASYNC16(sptr(&sm.c.Bs[(cc) % 3][rb2][segb]),                                   \
                   C + (size_t)(mtb + rb2) * D_ + (cc) * 32 + segb);                      \
        CP_ASYNC16(sptr(&sm.c.Bs[(cc) % 3][rb2][segb + 8]),                               \
                   C + (size_t)(mtb + rb2) * D_ + (cc) * 32 + segb + 8);                  \
        CP_COMMIT;                                                                        \
    } while (0)

        CL_ISSUE(0); CL_ISSUE(1);
        for (int c = 0; c < 32; c++) {
            CP_WAIT(1);
            __syncthreads();
            const int buf = c % 3;
#pragma unroll
            for (int ks = 0; ks < 2; ks++) {
                const int rowA = wb * 16 + (lane & 15);
                const int colh = ks * 16 + (lane >> 4) * 8;
                unsigned a[4];
                ldsm4(a[0], a[1], a[2], a[3], sptr(&sm.c.As[buf][rowA][colh]));
#pragma unroll
                for (int jj = 0; jj < 4; jj++) {
                    const int rowB = wd2 * 64 + jj * 16 + (lane & 15);
                    unsigned b0, b1, b2, b3;
                    ldsm4(b0, b1, b2, b3, sptr(&sm.c.Bs[buf][rowB][colh]));
                    mma16816(acc[2 * jj], a, b0, b2);
                    mma16816(acc[2 * jj + 1], a, b1, b3);
                }
            }
            if (c + 2 < 32) { CL_ISSUE(c + 2); } else { CP_COMMIT; }
        }
#undef CL_ISSUE

        int best0 = -1, best1 = -1;
#pragma unroll
        for (int jj = 0; jj < 4; jj++) {
#pragma unroll
            for (int t = 0; t < 2; t++) {
                const int m0 = mtb + wd2 * 64 + jj * 16 + t * 8 + (lane & 3) * 2;
                const float* ac = acc[2 * jj + t];
#pragma unroll
                for (int q = 0; q < 2; q++) {
                    best0 = max(best0, (((int)fabsf(ac[q])) << 12) | (4095 - (m0 + q)));
                    best1 = max(best1, (((int)fabsf(ac[2 + q])) << 12) | (4095 - (m0 + q)));
                }
            }
        }
        atomicMax(&g_amax[er * F_ + fc], best0);
        atomicMax(&g_amax[(er + 8) * F_ + fc], best1);
    }
    phase++; gbar(NCTA_ * phase);

    // ---- final outputs: [outcome(256)] [est(262144)] [iters] [conv] ----
    {
        const int g = cta * 256 + tid, gs = NCTA_ * 256;
        for (int i = g; i < B_ * F_; i += gs)
            if (i < out_size) out[i] = (float)(4095 - (g_amax[i] & 4095));
        for (int i = g; i < B_ * F_ * D_; i += gs) {
            int o = B_ * F_ + i;
            if (o < out_size) {
                int b = i / (F_ * D_);
                int f = (i / D_) % F_;
                int d = i % D_;
                out[o] = __half2float(g_est[cur][(f * B_ + b) * D_ + d]);
            }
        }
        if (cta == 0 && tid == 0) {
            int iters = 0, conv = 0;
            for (int i = 0; i < ITERS_; i++) {
                if (!conv) iters++;
                if (g_diff[i] == 0) conv = 1;
            }
            int o = B_ * F_ + B_ * F_ * D_;
            if (o < out_size) out[o] = (float)iters;
            if (o + 1 < out_size) out[o + 1] = (float)conv;
        }
    }
}

extern "C" void kernel_launch(void* const* d_in, const int* in_sizes, int n_in,
                              void* d_out, int out_size) {
    const float* inp = (const float*)d_in[0];
    const float* ie  = (const float*)d_in[1];
    const float* cb  = (const float*)d_in[2];

    k_prep<<<1024, 256>>>((const float4*)cb, inp, ie);
    k_trans8<<<dim3(M_ / 64, D_ / 64, F_), 256>>>();
    k_gram3<<<dim3(36, 4), 256>>>();
    k_mega<<<NCTA_, 256>>>((float*)d_out, out_size);
}